// round 10
// baseline (speedup 1.0000x reference)
#include <cuda_runtime.h>
#include <cstdint>

#define T_STEPS 512
#define BATCH   64
#define DIN     128
#define DH      1024
#define DOUT    256
#define RANK    64

#define CL      4            // cluster size (CTAs per batch-pair)
#define COLS    256          // DH / CL columns per CTA
#define BGRP    2            // batch elements per cluster
// grid = 128 CTAs = 32 clusters * 4; one wave on 148 SMs

// ---- packed f32x2 helpers (SASS FFMA2 path; PTX-only) ----------------------
#define FMA2(d, a, b) \
    asm("fma.rn.f32x2 %0, %1, %2, %0;" : "+l"(d) : "l"(a), "l"(b))
#define ADD2(d, a, b) \
    asm("add.rn.f32x2 %0, %1, %2;" : "=l"(d) : "l"(a), "l"(b))
#define PACK2(d, lo, hi) \
    asm("mov.b64 %0, {%1, %2};" : "=l"(d) : "f"(lo), "f"(hi))
#define UNPACK2(lo, hi, v) \
    asm("mov.b64 {%0, %1}, %2;" : "=f"(lo), "=f"(hi) : "l"(v))

// ---------------- C[m,n] = bias[n] + sum_k A[m,k]*B[n,k] --------------------
// A: [M,K] row-major, B: [N,K] row-major. Tiles 64x64, BK=32, k-pair FFMA2.
__global__ void __launch_bounds__(256) gemm_bt(const float* __restrict__ A,
                                               const float* __restrict__ Bm,
                                               const float* __restrict__ bias,
                                               float* __restrict__ C,
                                               int N, int K) {
    // sX2[kk][m] = (X[2kk][m], X[2kk+1][m])  -- k-pairs packed in float2
    __shared__ __align__(16) float2 sA2[16][70];
    __shared__ __align__(16) float2 sB2[16][70];
    const int tid = threadIdx.x;
    const int m0 = blockIdx.x * 64;
    const int n0 = blockIdx.y * 64;
    const int tx = tid & 15;
    const int ty = tid >> 4;
    const int lrow = tid >> 2;
    const int lkk  = (tid & 3) * 8;        // 8 consecutive k's per loader thread

    unsigned long long acc2[4][4];
#pragma unroll
    for (int i = 0; i < 4; i++)
#pragma unroll
        for (int j = 0; j < 4; j++) acc2[i][j] = 0ull;

    for (int k0 = 0; k0 < K; k0 += 32) {
        const float* ap = A + (size_t)(m0 + lrow) * K + k0 + lkk;
        const float* bp = Bm + (size_t)(n0 + lrow) * K + k0 + lkk;
        float4 a0 = *(const float4*)ap;
        float4 a1 = *(const float4*)(ap + 4);
        float4 b0 = *(const float4*)bp;
        float4 b1 = *(const float4*)(bp + 4);
        const int kk0 = lkk >> 1;
        sA2[kk0 + 0][lrow] = make_float2(a0.x, a0.y);
        sA2[kk0 + 1][lrow] = make_float2(a0.z, a0.w);
        sA2[kk0 + 2][lrow] = make_float2(a1.x, a1.y);
        sA2[kk0 + 3][lrow] = make_float2(a1.z, a1.w);
        sB2[kk0 + 0][lrow] = make_float2(b0.x, b0.y);
        sB2[kk0 + 1][lrow] = make_float2(b0.z, b0.w);
        sB2[kk0 + 2][lrow] = make_float2(b1.x, b1.y);
        sB2[kk0 + 3][lrow] = make_float2(b1.z, b1.w);
        __syncthreads();
#pragma unroll
        for (int kk = 0; kk < 16; kk++) {
            ulonglong2 av01 = *(const ulonglong2*)&sA2[kk][ty * 4];
            ulonglong2 av23 = *(const ulonglong2*)&sA2[kk][ty * 4 + 2];
            ulonglong2 bv01 = *(const ulonglong2*)&sB2[kk][tx * 4];
            ulonglong2 bv23 = *(const ulonglong2*)&sB2[kk][tx * 4 + 2];
            unsigned long long a_[4] = {av01.x, av01.y, av23.x, av23.y};
            unsigned long long b_[4] = {bv01.x, bv01.y, bv23.x, bv23.y};
#pragma unroll
            for (int i = 0; i < 4; i++)
#pragma unroll
                for (int j = 0; j < 4; j++) FMA2(acc2[i][j], a_[i], b_[j]);
        }
        __syncthreads();
    }

    float4 bias4 = *(const float4*)&bias[n0 + tx * 4];
    float bb[4] = {bias4.x, bias4.y, bias4.z, bias4.w};
#pragma unroll
    for (int i = 0; i < 4; i++) {
        float o[4];
#pragma unroll
        for (int j = 0; j < 4; j++) {
            float lo, hi;
            UNPACK2(lo, hi, acc2[i][j]);
            o[j] = lo + hi + bb[j];
        }
        float4 ov = make_float4(o[0], o[1], o[2], o[3]);
        *(float4*)&C[(size_t)(m0 + ty * 4 + i) * N + n0 + tx * 4] = ov;
    }
}

// ---------------- clustered recurrence (mbarrier sync, FFMA2 compute) --------
__device__ __forceinline__ uint32_t smem_u32(const void* p) {
    uint32_t a;
    asm("{ .reg .u64 t; cvta.to.shared.u64 t, %1; cvt.u32.u64 %0, t; }"
        : "=r"(a) : "l"(p));
    return a;
}

__device__ __forceinline__ void mbar_wait(uint32_t mbar, uint32_t parity) {
    asm volatile(
        "{\n\t"
        ".reg .pred P;\n\t"
        "W%=:\n\t"
        "mbarrier.try_wait.parity.acquire.cta.shared::cta.b64 P, [%0], %1, 0x989680;\n\t"
        "@P bra D%=;\n\t"
        "bra W%=;\n\t"
        "D%=:\n\t"
        "}"
        :: "r"(mbar), "r"(parity) : "memory");
}

__global__ void __launch_bounds__(256, 1) __cluster_dims__(CL, 1, 1)
rnn_recur(const float* __restrict__ U, const float* __restrict__ V,
          float* __restrict__ hidden) {
    __shared__ __align__(16) float pbuf[2][CL][BGRP][RANK];
    __shared__ __align__(16) float pcur[BGRP][RANK];
    __shared__ __align__(16) float sH[BGRP][COLS];
    __shared__ __align__(16) float sTmp[CL][BGRP][RANK];
    __shared__ __align__(8) unsigned long long mbar;

    const int tid  = threadIdx.x;
    const int rank = blockIdx.x & (CL - 1);
    const int clus = blockIdx.x >> 2;
    const int b0   = clus * BGRP;
    const int colbase = rank * COLS;
    const int col  = colbase + tid;

    const int rr = tid & 63;                    // phase iii: rank index
    const int qq = tid >> 6;                    // phase iii: 64-col chunk

    // ---- persistent register weights, packed over the reduction dim ----
    unsigned long long u2[RANK / 2];            // (u[2k], u[2k+1])
#pragma unroll
    for (int r4 = 0; r4 < 16; ++r4) {
        float4 t4 = *(const float4*)&U[(size_t)col * RANK + 4 * r4];
        PACK2(u2[2 * r4 + 0], t4.x, t4.y);
        PACK2(u2[2 * r4 + 1], t4.z, t4.w);
    }
    unsigned long long v2[32];                  // (v[2j], v[2j+1]) in qq-chunk
#pragma unroll
    for (int j4 = 0; j4 < 16; ++j4) {
        float4 t4 =
            *(const float4*)&V[(size_t)rr * DH + colbase + qq * 64 + 4 * j4];
        PACK2(v2[2 * j4 + 0], t4.x, t4.y);
        PACK2(v2[2 * j4 + 1], t4.z, t4.w);
    }

    // zero parity-0 buffer (p_0 = 0)
    for (int i = tid; i < CL * BGRP * RANK; i += 256)
        (&pbuf[0][0][0][0])[i] = 0.0f;

    const uint32_t mymbar = smem_u32(&mbar);
    if (tid == 0)
        asm volatile("mbarrier.init.shared.b64 [%0], %1;"
                     :: "r"(mymbar), "r"((unsigned)CL) : "memory");

    uint32_t mybuf = smem_u32(&pbuf[0][0][0][0]);
    uint32_t peerbuf[CL], peerbar[CL];
#pragma unroll
    for (int k = 0; k < CL; k++) {
        asm("mapa.shared::cluster.u32 %0, %1, %2;"
            : "=r"(peerbuf[k]) : "r"(mybuf), "r"(k));
        asm("mapa.shared::cluster.u32 %0, %1, %2;"
            : "=r"(peerbar[k]) : "r"(mymbar), "r"(k));
    }
    __syncthreads();
    asm volatile("barrier.cluster.arrive.aligned;" ::: "memory");
    asm volatile("barrier.cluster.wait.aligned;" ::: "memory");

    // preload c for t = 1
    float c0 = hidden[(size_t)b0 * DH + col];
    float c1 = hidden[(size_t)(b0 + 1) * DH + col];

    for (int t = 1; t <= T_STEPS; ++t) {
        float* row = hidden + (size_t)(t - 1) * BATCH * DH;

        if (t >= 2) {
            mbar_wait(mymbar, (unsigned)(t & 1));
            if (tid == 0)
                asm volatile("fence.acq_rel.cluster;" ::: "memory");
            __syncthreads();
        }

        // reduce the 4 rank-partials of p_{t-1}
        const int par = (t - 1) & 1;
        if (tid < BGRP * RANK) {
            int b = tid >> 6, r = tid & 63;
            pcur[b][r] = pbuf[par][0][b][r] + pbuf[par][1][b][r]
                       + pbuf[par][2][b][r] + pbuf[par][3][b][r];
        }
        __syncthreads();

        // ---- phase ii: g = c + u . p ; h = relu(g)  (FFMA2, even/odd r) ----
        unsigned long long ga0 = 0ull, ga1 = 0ull, gb0 = 0ull, gb1 = 0ull;
        const ulonglong2* pa4 = (const ulonglong2*)pcur[0];
        const ulonglong2* pb4 = (const ulonglong2*)pcur[1];
#pragma unroll
        for (int r4 = 0; r4 < 16; ++r4) {
            ulonglong2 pa = pa4[r4];             // (p[4r4],p[4r4+1]),(p+2,p+3)
            ulonglong2 pb = pb4[r4];
            FMA2(ga0, u2[2 * r4 + 0], pa.x);
            FMA2(ga1, u2[2 * r4 + 1], pa.y);
            FMA2(gb0, u2[2 * r4 + 0], pb.x);
            FMA2(gb1, u2[2 * r4 + 1], pb.y);
        }
        ADD2(ga0, ga0, ga1);
        ADD2(gb0, gb0, gb1);
        float galo, gahi, gblo, gbhi;
        UNPACK2(galo, gahi, ga0);
        UNPACK2(gblo, gbhi, gb0);
        float h0 = fmaxf(c0 + galo + gahi, 0.0f);
        float h1 = fmaxf(c1 + gblo + gbhi, 0.0f);
        row[(size_t)b0 * DH + col] = h0;          // in-place: c -> h
        row[(size_t)(b0 + 1) * DH + col] = h1;
        sH[0][tid] = h0;
        sH[1][tid] = h1;

        // prefetch c for step t+1 (consumed next step; long latency cover)
        if (t < T_STEPS) {
            const float* rowN = hidden + (size_t)t * BATCH * DH;
            c0 = rowN[(size_t)b0 * DH + col];
            c1 = rowN[(size_t)(b0 + 1) * DH + col];
        }
        __syncthreads();

        // ---- phase iii: pp[b][rr] over this thread's 64-col chunk (FFMA2) --
        unsigned long long aa0 = 0ull, aa1 = 0ull, ab0 = 0ull, ab1 = 0ull;
        const ulonglong2* h0q = (const ulonglong2*)&sH[0][qq * 64];
        const ulonglong2* h1q = (const ulonglong2*)&sH[1][qq * 64];
#pragma unroll
        for (int j4 = 0; j4 < 16; ++j4) {
            ulonglong2 ha = h0q[j4];
            ulonglong2 hb = h1q[j4];
            FMA2(aa0, v2[2 * j4 + 0], ha.x);
            FMA2(aa1, v2[2 * j4 + 1], ha.y);
            FMA2(ab0, v2[2 * j4 + 0], hb.x);
            FMA2(ab1, v2[2 * j4 + 1], hb.y);
        }
        ADD2(aa0, aa0, aa1);
        ADD2(ab0, ab0, ab1);
        float alo, ahi, blo, bhi;
        UNPACK2(alo, ahi, aa0);
        UNPACK2(blo, bhi, ab0);
        sTmp[qq][0][rr] = alo + ahi;
        sTmp[qq][1][rr] = blo + bhi;
        __syncthreads();

        // ---- fold q-chunks + scatter to all 4 cluster CTAs via DSMEM -------
        const int wpar = t & 1;
        if (tid < BGRP * RANK) {
            int b = tid >> 6, r = tid & 63;
            float s = sTmp[0][b][r] + sTmp[1][b][r]
                    + sTmp[2][b][r] + sTmp[3][b][r];
            uint32_t off =
                (uint32_t)(((wpar * CL + rank) * BGRP + b) * RANK + r) * 4u;
#pragma unroll
            for (int k = 0; k < CL; k++)
                asm volatile("st.shared::cluster.f32 [%0], %1;"
                             :: "r"(peerbuf[k] + off), "f"(s) : "memory");
        }
        __syncthreads();
        if (tid == 0) {
            asm volatile("fence.acq_rel.cluster;" ::: "memory");
#pragma unroll
            for (int k = 0; k < CL; k++)
                asm volatile("mbarrier.arrive.shared::cluster.b64 _, [%0];"
                             :: "r"(peerbar[k]) : "memory");
        }
    }

    asm volatile("barrier.cluster.arrive.aligned;" ::: "memory");
    asm volatile("barrier.cluster.wait.aligned;" ::: "memory");
}

// ---------------- launch -----------------------------------------------------
extern "C" void kernel_launch(void* const* d_in, const int* in_sizes, int n_in,
                              void* d_out, int out_size) {
    (void)in_sizes; (void)n_in; (void)out_size;
    const float* x  = (const float*)d_in[0];
    const float* Wi = (const float*)d_in[1];
    const float* U  = (const float*)d_in[2];
    const float* V  = (const float*)d_in[3];
    const float* bh = (const float*)d_in[4];
    const float* Wo = (const float*)d_in[5];
    const float* bo = (const float*)d_in[6];

    float* hidden = (float*)d_out;                                   // [T,B,DH]
    float* outp   = hidden + (size_t)T_STEPS * BATCH * DH;           // [T,B,DOUT]

    // c = x @ Wi^T + bh  (written into hidden region, consumed in place)
    dim3 gA(T_STEPS * BATCH / 64, DH / 64);
    gemm_bt<<<gA, 256>>>(x, Wi, bh, hidden, DH, DIN);

    // serial recurrence: 32 clusters x 4 CTAs, DSMEM rank exchange
    rnn_recur<<<BATCH / BGRP * CL, 256>>>(U, V, hidden);

    // output = hidden @ Wo^T + bo
    dim3 gC(T_STEPS * BATCH / 64, DOUT / 64);
    gemm_bt<<<gC, 256>>>(hidden, Wo, bo, outp, DOUT, DH);
}